// round 15
// baseline (speedup 1.0000x reference)
#include <cuda_runtime.h>
#include <cuda_fp16.h>
#include <cstdint>
#include <math.h>

#define B_ 32
#define N_ 1024
#define C_ 64
#define BN (B_ * N_)

typedef unsigned long long ULL;

// device-global scratch (allocation-free rule)
__device__ uint4    g_hpk4[B_ * C_ * 256];   // packed (hh2,hl2)x2 fp16 pair slots
__device__ uint4    g_wpk4[32 * 64];         // packed tf32 W tiles (hi,lo,hi+4,lo+4)
__device__ float    g_ssrc[BN];
__device__ float    g_sdst[BN];
__device__ unsigned g_smaxu[B_];
__device__ uint32_t g_mask[N_ * N_ / 32];    // adj>0.5 bitmask

__device__ __forceinline__ uint32_t smem_u32(const void* p) {
    uint32_t a;
    asm("{ .reg .u64 t; cvta.to.shared.u64 t, %1; cvt.u32.u64 %0, t; }" : "=r"(a) : "l"(p));
    return a;
}
__device__ __forceinline__ void cp_async16(uint32_t dst, const void* src) {
    asm volatile("cp.async.cg.shared.global [%0], [%1], 16;" :: "r"(dst), "l"(src));
}
#define CP_COMMIT() asm volatile("cp.async.commit_group;" ::: "memory")
#define CP_WAIT2()  asm volatile("cp.async.wait_group 2;" ::: "memory")

__device__ __forceinline__ void mma_f16(float* d,
                                        uint32_t a0, uint32_t a1, uint32_t a2, uint32_t a3,
                                        uint32_t b0, uint32_t b1) {
    asm volatile(
        "mma.sync.aligned.m16n8k16.row.col.f32.f16.f16.f32 "
        "{%0,%1,%2,%3},{%4,%5,%6,%7},{%8,%9},{%0,%1,%2,%3};"
        : "+f"(d[0]), "+f"(d[1]), "+f"(d[2]), "+f"(d[3])
        : "r"(a0), "r"(a1), "r"(a2), "r"(a3), "r"(b0), "r"(b1));
}
__device__ __forceinline__ void mma_tf32(float* d,
                                         uint32_t a0, uint32_t a1, uint32_t a2, uint32_t a3,
                                         uint32_t b0, uint32_t b1) {
    asm volatile(
        "mma.sync.aligned.m16n8k8.row.col.f32.tf32.tf32.f32 "
        "{%0,%1,%2,%3},{%4,%5,%6,%7},{%8,%9},{%0,%1,%2,%3};"
        : "+f"(d[0]), "+f"(d[1]), "+f"(d[2]), "+f"(d[3])
        : "r"(a0), "r"(a1), "r"(a2), "r"(a3), "r"(b0), "r"(b1));
}
__device__ __forceinline__ uint32_t h2u(__half2 h) { return *(uint32_t*)&h; }

__device__ __forceinline__ float2 mul2f(ULL ab, ULL ef) {
    ULL q;
    asm("mul.rn.f32x2 %0, %1, %2;" : "=l"(q) : "l"(ab), "l"(ef));
    float2 r;
    asm("mov.b64 {%0,%1}, %2;" : "=f"(r.x), "=f"(r.y) : "l"(q));
    return r;
}
__device__ __forceinline__ ULL pack2f(float x, float y) {
    ULL v; asm("mov.b64 %0, {%1,%2};" : "=l"(v) : "f"(x), "f"(y)); return v;
}
__device__ __forceinline__ ULL ld_s64(uint32_t addr) {
    ULL v; asm volatile("ld.shared.b64 %0, [%1];" : "=l"(v) : "r"(addr)); return v;
}
__device__ __forceinline__ float trunc16(float v) {
    return __uint_as_float(__float_as_uint(v) & 0xFFFFE000u);
}
__device__ __forceinline__ unsigned enc_f(float f) {
    unsigned u = __float_as_uint(f);
    return (u & 0x80000000u) ? ~u : (u | 0x80000000u);
}
__device__ __forceinline__ float dec_f(unsigned u) {
    return (u & 0x80000000u) ? __uint_as_float(u ^ 0x80000000u) : __uint_as_float(~u);
}

// ---------------------------------------------------------------------------
// Kernel W: build packed tf32 W tiles in global (tiny, runs once per launch)
// ---------------------------------------------------------------------------
__global__ void __launch_bounds__(256) wprep_kernel(const float* __restrict__ W) {
    const int e = blockIdx.x * 256 + threadIdx.x;  // 0..2047
    const int kq = e >> 6;
    const int n = e & 63;
    const int k = (kq >> 2) * 8 + (kq & 3);
    const float w0 = __ldg(W + k * 64 + n);
    const float w1 = __ldg(W + (k + 4) * 64 + n);
    const float h0 = trunc16(w0), h1 = trunc16(w1);
    g_wpk4[kq * 64 + n] = make_uint4(__float_as_uint(h0), __float_as_uint(w0 - h0),
                                     __float_as_uint(h1), __float_as_uint(w1 - h1));
}

// ---------------------------------------------------------------------------
// Kernel A: h = input @ W via 3xTF32 mma.sync (W fragments from L1-resident
// global), fused adj bitmask + dots + batch max; hpk pairs built directly
// from D-fragments via shfl (no fp32 h staging). smem = 35KB -> 2-3 CTAs/SM.
// ---------------------------------------------------------------------------
#define ISTR 68                       // float stride of input tile
#define PSTRP 66                      // uint2 stride of pair tile
#define GS_IN  0                      // float[128*68] = 34816 B (reused as ptile)
#define GS_AV  34816                  // float[128]
#define GS_TOTAL (GS_AV + 512)

__global__ void __launch_bounds__(256) gemm_h_kernel(const float* __restrict__ in,
                                                     const float* __restrict__ av,
                                                     const float* __restrict__ adj) {
    extern __shared__ char gs[];
    float* tin = (float*)(gs + GS_IN);
    float* avs = (float*)(gs + GS_AV);
    uint2* ptile = (uint2*)(gs + GS_IN);    // overlays tin after k-loop
    __shared__ float red[8];

    const int t = threadIdx.x;
    const int lane = t & 31;
    const int wid = t >> 5;
    const int r0 = lane >> 2;
    const int c0 = lane & 3;
    const int row0 = blockIdx.x * 128;
    const int b = blockIdx.x >> 3;
    const int n0 = row0 & 1023;

    // adj gate loads early
    const int gw2 = (blockIdx.x * 8 + wid) * 2;
    float mv[16];
#pragma unroll
    for (int j = 0; j < 2; j++)
#pragma unroll
        for (int q = 0; q < 8; q++)
            mv[j * 8 + q] = __ldg(adj + (size_t)(gw2 + j) * 256 + q * 32 + lane);

    // stage input tile 128x64 -> stride-68 smem
#pragma unroll
    for (int i = 0; i < 8; i++) {
        const int e = t + 256 * i;
        const int r = e >> 4;
        const int c4 = (e & 15) * 4;
        const float4 v = __ldg((const float4*)(in + (size_t)(row0 + r) * 64 + c4));
        *(float4*)&tin[r * ISTR + c4] = v;
    }
    if (t < 128) avs[t] = __ldg(av + t);
    __syncthreads();

#pragma unroll
    for (int j = 0; j < 16; j++) {
        const uint32_t m = __ballot_sync(0xffffffffu, mv[j] > 0.5f);
        if (lane == 0) g_mask[(gw2 + (j >> 3)) * 8 + (j & 7)] = m;
    }

    // 3xTF32 MMA k-loop: warp owns rows row0 + wid*16 .. +15
    float D[8][4];
#pragma unroll
    for (int nb = 0; nb < 8; nb++)
#pragma unroll
        for (int q = 0; q < 4; q++) D[nb][q] = 0.f;

    const float* arow = tin + (wid * 16 + r0) * ISTR;
#pragma unroll
    for (int kk = 0; kk < 8; kk++) {
        const int kb = kk * 8 + c0;
        const float i0 = arow[kb];
        const float i1 = arow[8 * ISTR + kb];
        const float i2 = arow[kb + 4];
        const float i3 = arow[8 * ISTR + kb + 4];
        const float h0 = trunc16(i0), h1 = trunc16(i1), h2 = trunc16(i2), h3 = trunc16(i3);
        const uint32_t ah0 = __float_as_uint(h0), ah1 = __float_as_uint(h1);
        const uint32_t ah2 = __float_as_uint(h2), ah3 = __float_as_uint(h3);
        const uint32_t al0 = __float_as_uint(i0 - h0), al1 = __float_as_uint(i1 - h1);
        const uint32_t al2 = __float_as_uint(i2 - h2), al3 = __float_as_uint(i3 - h3);

        const uint4* wrow = g_wpk4 + (kk * 4 + c0) * 64 + r0;
#pragma unroll
        for (int nb = 0; nb < 8; nb++) {
            const uint4 bv = __ldg(wrow + nb * 8);
            mma_tf32(D[nb], ah0, ah1, ah2, ah3, bv.x, bv.z);  // ah * wh
            mma_tf32(D[nb], ah0, ah1, ah2, ah3, bv.y, bv.w);  // ah * wl
            mma_tf32(D[nb], al0, al1, al2, al3, bv.x, bv.z);  // al * wh
        }
    }

    // dots from D fragments
    float ssA = 0.f, ssB = 0.f, sdA = 0.f, sdB = 0.f;
#pragma unroll
    for (int nb = 0; nb < 8; nb++) {
        const int c = nb * 8 + 2 * c0;
        ssA += D[nb][0] * avs[c] + D[nb][1] * avs[c + 1];
        ssB += D[nb][2] * avs[c] + D[nb][3] * avs[c + 1];
        sdA += D[nb][0] * avs[64 + c] + D[nb][1] * avs[64 + c + 1];
        sdB += D[nb][2] * avs[64 + c] + D[nb][3] * avs[64 + c + 1];
    }
#pragma unroll
    for (int o = 1; o <= 2; o <<= 1) {
        ssA += __shfl_xor_sync(0xffffffffu, ssA, o);
        ssB += __shfl_xor_sync(0xffffffffu, ssB, o);
        sdA += __shfl_xor_sync(0xffffffffu, sdA, o);
        sdB += __shfl_xor_sync(0xffffffffu, sdB, o);
    }
    if (c0 == 0) {
        const int rw = row0 + wid * 16 + r0;
        g_ssrc[rw] = ssA;
        g_ssrc[rw + 8] = ssB;
        g_sdst[rw] = sdA;
        g_sdst[rw + 8] = sdB;
    }
    float sdm = fmaxf(sdA, sdB);
#pragma unroll
    for (int o = 4; o <= 16; o <<= 1) sdm = fmaxf(sdm, __shfl_xor_sync(0xffffffffu, sdm, o));
    if (lane == 0) red[wid] = sdm;

    __syncthreads();   // k-loop tin reads done; safe to overwrite with ptile
    if (t == 0) {
        float m = red[0];
#pragma unroll
        for (int i = 1; i < 8; i++) m = fmaxf(m, red[i]);
        atomicMax(&g_smaxu[b], enc_f(m));
    }

    // pair-build straight from D-fragments: lane r0 (even) pairs with r0+1
    // (lane^4) for rows (base+r0, base+r0+1) and (base+8+r0, base+8+r0+1).
    {
        const int qa = wid * 8 + (r0 >> 1);        // pair idx rows base+r0,+1
        const int qb = qa + 4;                     // pair idx rows base+8+r0,+1
        const int qa32 = qa & 31, qb32 = qb & 31;
        const int pra = (qa >> 5) * 32 + (((qa32 >> 3) * 4 + (qa32 & 3)) * 2 + ((qa32 >> 2) & 1));
        const int prb = (qb >> 5) * 32 + (((qb32 >> 3) * 4 + (qb32 & 3)) * 2 + ((qb32 >> 2) & 1));
        const bool even = (r0 & 1) == 0;
#pragma unroll
        for (int nb = 0; nb < 8; nb++) {
            const float p0 = __shfl_xor_sync(0xffffffffu, D[nb][0], 4);
            const float p1 = __shfl_xor_sync(0xffffffffu, D[nb][1], 4);
            const float p2 = __shfl_xor_sync(0xffffffffu, D[nb][2], 4);
            const float p3 = __shfl_xor_sync(0xffffffffu, D[nb][3], 4);
            if (even) {
                const int col = nb * 8 + 2 * c0;
                const float vals[4][2] = {{D[nb][0], p0}, {D[nb][1], p1},
                                          {D[nb][2], p2}, {D[nb][3], p3}};
                const int cols[4] = {col, col + 1, col, col + 1};
                const int prs[4] = {pra, pra, prb, prb};
#pragma unroll
                for (int u = 0; u < 4; u++) {
                    const float va = vals[u][0], vb = vals[u][1];
                    const __half ha = __float2half_rn(va);
                    const __half hb = __float2half_rn(vb);
                    uint2 pk;
                    pk.x = h2u(__halves2half2(ha, hb));
                    pk.y = h2u(__floats2half2_rn(va - __half2float(ha),
                                                 vb - __half2float(hb)));
                    ptile[cols[u] * PSTRP + prs[u]] = pk;
                }
            }
        }
    }
    __syncthreads();

    // coalesced copy out (uint4 = 2 consecutive permuted slots)
    const uint4* pt4 = (const uint4*)ptile;
#pragma unroll
    for (int i = 0; i < 8; i++) {
        const int e = t + 256 * i;       // 0..2047
        const int c = e >> 5;
        const int m = e & 31;
        g_hpk4[((size_t)b * 64 + c) * 256 + n0 / 4 + m] = pt4[c * 33 + m];
    }
}

// ---------------------------------------------------------------------------
// Kernel D: fused attention. Prologue computes whole-batch EF + per-row A,B
// (prep kernel eliminated); bitmask gates; 4-deep cp.async; 3xFP16 m16n8k16.
// ---------------------------------------------------------------------------
#define PKS4 20                              // uint4 stride per c-row
#define PKBUF4 (64 * PKS4)                   // uint4 per buffer (1280)
#define EFOFF (4 * PKBUF4 * 16)              // 81920
#define SMEM_DYN (EFOFF + 1024 * 8)          // + float2[1024] = 90112
#define ONES2 0x3C003C00u

__global__ void __launch_bounds__(256, 2) attn_kernel(float* __restrict__ out) {
    extern __shared__ char sm[];
    uint4* pkbase = (uint4*)sm;
    float2* efs = (float2*)(sm + EFOFF);
    const uint32_t ef_addr0 = smem_u32(efs);

    const int b = blockIdx.y;
    const int i0 = blockIdx.x * 128;
    const int t = threadIdx.x;
    const int w = t >> 5;
    const int lane = t & 31;
    const int r0 = lane >> 2;
    const int c0 = lane & 3;

    const int irow0 = i0 + w * 16 + r0;
    const int irow1 = irow0 + 8;

    auto stage = [&](int jt) {
        const int buf = jt & 3;
        uint4* pkd = pkbase + buf * PKBUF4;
#pragma unroll
        for (int q = 0; q < 4; q++) {
            const int cid = q * 256 + t;
            const int c = cid >> 4;
            const int part = cid & 15;
            cp_async16(smem_u32(&pkd[c * PKS4 + part]),
                       &g_hpk4[((size_t)b * 64 + c) * 256 + jt * 16 + part]);
        }
    };

    stage(0); CP_COMMIT();
    stage(1); CP_COMMIT();
    stage(2); CP_COMMIT();

    // prologue: whole-batch EF into smem; per-row A,B
    const float S = dec_f(g_smaxu[b]);
#pragma unroll
    for (int k = 0; k < 4; k++) {
        const int j = t + k * 256;
        const float sd = g_sdst[b * N_ + j];
        efs[j] = make_float2(__expf(sd), __expf(0.2f * sd));
    }
    const float ss0 = g_ssrc[b * N_ + irow0];
    const float ss1 = g_ssrc[b * N_ + irow1];
    float mm0 = ss0 + S; mm0 = mm0 >= 0.f ? mm0 : 0.2f * mm0;
    float mm1 = ss1 + S; mm1 = mm1 >= 0.f ? mm1 : 0.2f * mm1;
    const ULL AB0 = pack2f(__expf(ss0 - mm0), __expf(0.2f * ss0 - mm0));
    const ULL AB1 = pack2f(__expf(ss1 - mm1), __expf(0.2f * ss1 - mm1));

    float D[8][4];
#pragma unroll
    for (int nb = 0; nb < 8; nb++)
#pragma unroll
        for (int q = 0; q < 4; q++) D[nb][q] = 0.f;
    float Dl[4] = {0.f, 0.f, 0.f, 0.f};

    const uint32_t* mk0 = g_mask + (size_t)irow0 * 32;
    const uint32_t* mk1 = g_mask + (size_t)irow1 * 32;

    uint32_t mw00 = __ldg(mk0 + 0), mw01 = __ldg(mk0 + 1);
    uint32_t mw10 = __ldg(mk1 + 0), mw11 = __ldg(mk1 + 1);

    for (int jt = 0; jt < 16; jt++) {
        CP_WAIT2();
        __syncthreads();   // also makes efs visible on the first iteration

        if (jt + 3 < 16) stage(jt + 3);
        CP_COMMIT();

        const int jw = (jt < 15) ? (jt + 1) * 2 : 0;
        const uint32_t nw00 = __ldg(mk0 + jw), nw01 = __ldg(mk0 + jw + 1);
        const uint32_t nw10 = __ldg(mk1 + jw), nw11 = __ldg(mk1 + jw + 1);

        const int buf = jt & 3;
        const uint4* pkp = pkbase + buf * PKBUF4;
        const uint32_t efbase = ef_addr0 + (jt * 64 + 2 * c0) * 8;

        const uint32_t wsh00 = mw00 >> (2 * c0), wsh01 = mw01 >> (2 * c0);
        const uint32_t wsh10 = mw10 >> (2 * c0), wsh11 = mw11 >> (2 * c0);

#pragma unroll
        for (int ks = 0; ks < 4; ks++) {
            const uint32_t ea_addr = efbase + ks * 128;
            const ULL ea = ld_s64(ea_addr);
            const ULL eb = ld_s64(ea_addr + 8);
            const ULL ec = ld_s64(ea_addr + 64);
            const ULL ed = ld_s64(ea_addr + 72);
            const uint32_t ws0 = (ks < 2) ? wsh00 : wsh01;
            const uint32_t ws1 = (ks < 2) ? wsh10 : wsh11;
            const int bo = (ks & 1) << 4;

            float2 q;
            q = mul2f(AB0, ea); float p00 = fmaxf(q.x, q.y);
            q = mul2f(AB0, eb); float p01 = fmaxf(q.x, q.y);
            q = mul2f(AB0, ec); float p02 = fmaxf(q.x, q.y);
            q = mul2f(AB0, ed); float p03 = fmaxf(q.x, q.y);
            q = mul2f(AB1, ea); float p10 = fmaxf(q.x, q.y);
            q = mul2f(AB1, eb); float p11 = fmaxf(q.x, q.y);
            q = mul2f(AB1, ec); float p12 = fmaxf(q.x, q.y);
            q = mul2f(AB1, ed); float p13 = fmaxf(q.x, q.y);

            p00 = ((ws0 >> (bo + 0)) & 1u) ? p00 : 0.f;
            p01 = ((ws0 >> (bo + 1)) & 1u) ? p01 : 0.f;
            p02 = ((ws0 >> (bo + 8)) & 1u) ? p02 : 0.f;
            p03 = ((ws0 >> (bo + 9)) & 1u) ? p03 : 0.f;
            p10 = ((ws1 >> (bo + 0)) & 1u) ? p10 : 0.f;
            p11 = ((ws1 >> (bo + 1)) & 1u) ? p11 : 0.f;
            p12 = ((ws1 >> (bo + 8)) & 1u) ? p12 : 0.f;
            p13 = ((ws1 >> (bo + 9)) & 1u) ? p13 : 0.f;

            const float t00 = trunc16(p00), t01 = trunc16(p01);
            const float t02 = trunc16(p02), t03 = trunc16(p03);
            const float t10 = trunc16(p10), t11 = trunc16(p11);
            const float t12 = trunc16(p12), t13 = trunc16(p13);

            const uint32_t uh0 = h2u(__floats2half2_rn(t00, t01));
            const uint32_t uh1 = h2u(__floats2half2_rn(t10, t11));
            const uint32_t uh2 = h2u(__floats2half2_rn(t02, t03));
            const uint32_t uh3 = h2u(__floats2half2_rn(t12, t13));
            const uint32_t ul0 = h2u(__floats2half2_rn(p00 - t00, p01 - t01));
            const uint32_t ul1 = h2u(__floats2half2_rn(p10 - t10, p11 - t11));
            const uint32_t ul2 = h2u(__floats2half2_rn(p02 - t02, p03 - t03));
            const uint32_t ul3 = h2u(__floats2half2_rn(p12 - t12, p13 - t13));

            // l = Σ(ph + pl) — both terms (ph-only measured too lossy in R12)
            mma_f16(Dl, uh0, uh1, uh2, uh3, ONES2, ONES2);
            mma_f16(Dl, ul0, ul1, ul2, ul3, ONES2, ONES2);

#pragma unroll
            for (int nb = 0; nb < 8; nb++) {
                const uint4 bv = pkp[(nb * 8 + r0) * PKS4 + ks * 4 + c0];
                mma_f16(D[nb], uh0, uh1, uh2, uh3, bv.x, bv.z);  // ph * hh
                mma_f16(D[nb], uh0, uh1, uh2, uh3, bv.y, bv.w);  // ph * hl
                mma_f16(D[nb], ul0, ul1, ul2, ul3, bv.x, bv.z);  // pl * hh
            }
        }

        mw00 = nw00; mw01 = nw01; mw10 = nw10; mw11 = nw11;
    }

    const float inv0 = 1.0f / Dl[0];
    const float inv1 = 1.0f / Dl[2];

    float2* o0 = (float2*)(out + ((size_t)b * N_ + irow0) * C_ + 2 * c0);
    float2* o1 = (float2*)(out + ((size_t)b * N_ + irow1) * C_ + 2 * c0);
#pragma unroll
    for (int nb = 0; nb < 8; nb++) {
        float v0 = D[nb][0] * inv0;
        float v1 = D[nb][1] * inv0;
        float v2 = D[nb][2] * inv1;
        float v3 = D[nb][3] * inv1;
        v0 = v0 > 0.f ? v0 : (__expf(v0) - 1.0f);
        v1 = v1 > 0.f ? v1 : (__expf(v1) - 1.0f);
        v2 = v2 > 0.f ? v2 : (__expf(v2) - 1.0f);
        v3 = v3 > 0.f ? v3 : (__expf(v3) - 1.0f);
        o0[nb * 4] = make_float2(v0, v1);
        o1[nb * 4] = make_float2(v2, v3);
    }
}

// ---------------------------------------------------------------------------
extern "C" void kernel_launch(void* const* d_in, const int* in_sizes, int n_in,
                              void* d_out, int out_size) {
    const float* input = (const float*)d_in[0];  // (32,1024,64)
    const float* adj   = (const float*)d_in[1];  // (1024,1024)
    const float* W     = (const float*)d_in[2];  // (64,64)
    const float* a     = (const float*)d_in[3];  // (128,1)
    float* out = (float*)d_out;

    cudaFuncSetAttribute(attn_kernel, cudaFuncAttributeMaxDynamicSharedMemorySize, SMEM_DYN);

    wprep_kernel<<<8, 256>>>(W);
    gemm_h_kernel<<<BN / 128, 256, GS_TOTAL>>>(input, a, adj);
    attn_kernel<<<dim3(N_ / 128, B_), 256, SMEM_DYN>>>(out);
}

// round 16
// speedup vs baseline: 1.1111x; 1.1111x over previous
#include <cuda_runtime.h>
#include <cuda_fp16.h>
#include <cstdint>
#include <math.h>

#define B_ 32
#define N_ 1024
#define C_ 64
#define BN (B_ * N_)

typedef unsigned long long ULL;

// device-global scratch (allocation-free rule)
__device__ uint4    g_hpk4[B_ * C_ * 256];   // packed (hh2,hl2)x2 fp16 pair slots
__device__ float    g_ssrc[BN];
__device__ float    g_sdst[BN];
__device__ unsigned g_smaxu[B_];
__device__ float2   g_AB[BN];                // (A, B) per row
__device__ float2   g_EF[BN];                // (E, F) per col
__device__ uint32_t g_mask[N_ * N_ / 32];    // adj>0.5 bitmask

__device__ __forceinline__ uint32_t smem_u32(const void* p) {
    uint32_t a;
    asm("{ .reg .u64 t; cvta.to.shared.u64 t, %1; cvt.u32.u64 %0, t; }" : "=r"(a) : "l"(p));
    return a;
}
__device__ __forceinline__ void cp_async16(uint32_t dst, const void* src) {
    asm volatile("cp.async.cg.shared.global [%0], [%1], 16;" :: "r"(dst), "l"(src));
}
#define CP_COMMIT() asm volatile("cp.async.commit_group;" ::: "memory")
#define CP_WAIT2()  asm volatile("cp.async.wait_group 2;" ::: "memory")

__device__ __forceinline__ void mma_f16(float* d,
                                        uint32_t a0, uint32_t a1, uint32_t a2, uint32_t a3,
                                        uint32_t b0, uint32_t b1) {
    asm volatile(
        "mma.sync.aligned.m16n8k16.row.col.f32.f16.f16.f32 "
        "{%0,%1,%2,%3},{%4,%5,%6,%7},{%8,%9},{%0,%1,%2,%3};"
        : "+f"(d[0]), "+f"(d[1]), "+f"(d[2]), "+f"(d[3])
        : "r"(a0), "r"(a1), "r"(a2), "r"(a3), "r"(b0), "r"(b1));
}
__device__ __forceinline__ void mma_tf32(float* d,
                                         uint32_t a0, uint32_t a1, uint32_t a2, uint32_t a3,
                                         uint32_t b0, uint32_t b1) {
    asm volatile(
        "mma.sync.aligned.m16n8k8.row.col.f32.tf32.tf32.f32 "
        "{%0,%1,%2,%3},{%4,%5,%6,%7},{%8,%9},{%0,%1,%2,%3};"
        : "+f"(d[0]), "+f"(d[1]), "+f"(d[2]), "+f"(d[3])
        : "r"(a0), "r"(a1), "r"(a2), "r"(a3), "r"(b0), "r"(b1));
}
__device__ __forceinline__ uint32_t h2u(__half2 h) { return *(uint32_t*)&h; }

__device__ __forceinline__ float2 mul2f(ULL ab, ULL ef) {
    ULL q;
    asm("mul.rn.f32x2 %0, %1, %2;" : "=l"(q) : "l"(ab), "l"(ef));
    float2 r;
    asm("mov.b64 {%0,%1}, %2;" : "=f"(r.x), "=f"(r.y) : "l"(q));
    return r;
}
__device__ __forceinline__ ULL pack2f(float x, float y) {
    ULL v; asm("mov.b64 %0, {%1,%2};" : "=l"(v) : "f"(x), "f"(y)); return v;
}
__device__ __forceinline__ ULL ld_s64(uint32_t addr) {
    ULL v; asm volatile("ld.shared.b64 %0, [%1];" : "=l"(v) : "r"(addr)); return v;
}
__device__ __forceinline__ float trunc16(float v) {
    return __uint_as_float(__float_as_uint(v) & 0xFFFFE000u);
}
__device__ __forceinline__ unsigned enc_f(float f) {
    unsigned u = __float_as_uint(f);
    return (u & 0x80000000u) ? ~u : (u | 0x80000000u);
}
__device__ __forceinline__ float dec_f(unsigned u) {
    return (u & 0x80000000u) ? __uint_as_float(u ^ 0x80000000u) : __uint_as_float(~u);
}

// ---------------------------------------------------------------------------
// Kernel A: h = input @ W via 3xTF32 mma.sync. 64 rows / 128 threads per
// block -> smem 51.7KB -> 4 CTAs/SM (fixes R14's 1-CTA DRAM-latency wall).
// Fused: adj bitmask, dots, batch max; pairs built from D-fragments via shfl.
// ---------------------------------------------------------------------------
#define ISTR 68                       // float stride of input tile
#define WSTR 66                       // uint4 stride of Wpk tile
#define PSTR2 34                      // uint2 stride of pair tile (even)
#define GS_WPK 0                      // uint4[32*66]  = 33792 B (ptile overlays)
#define GS_IN  33792                  // float[64*68]  = 17408 B
#define GS_AV  (33792 + 17408)        // float[128]
#define GS_TOTAL (GS_AV + 512)

__global__ void __launch_bounds__(128) gemm_h_kernel(const float* __restrict__ in,
                                                     const float* __restrict__ W,
                                                     const float* __restrict__ av,
                                                     const float* __restrict__ adj) {
    extern __shared__ char gs[];
    uint4* wpk = (uint4*)(gs + GS_WPK);
    float* tin = (float*)(gs + GS_IN);
    float* avs = (float*)(gs + GS_AV);
    uint2* ptile = (uint2*)(gs + GS_WPK);   // overlays dead Wpk after k-loop
    __shared__ float red[4];

    const int t = threadIdx.x;              // 0..127
    const int lane = t & 31;
    const int wid = t >> 5;                 // 0..3
    const int r0 = lane >> 2;
    const int c0 = lane & 3;
    const int row0 = blockIdx.x * 64;
    const int b = blockIdx.x >> 4;
    const int n0 = row0 & 1023;

    // adj gate loads early: warp-slot gw4 covers 512 floats -> 16 mask words
    const int gw4 = blockIdx.x * 4 + wid;   // 0..2047
    float mv[16];
#pragma unroll
    for (int q = 0; q < 16; q++)
        mv[q] = __ldg(adj + (size_t)gw4 * 512 + q * 32 + lane);

    // stage input tile 64x64 -> stride-68 smem (1024 float4, 8 per thread)
#pragma unroll
    for (int i = 0; i < 8; i++) {
        const int e = t + 128 * i;
        const int r = e >> 4;
        const int c4 = (e & 15) * 4;
        const float4 v = __ldg((const float4*)(in + (size_t)(row0 + r) * 64 + c4));
        *(float4*)&tin[r * ISTR + c4] = v;
    }
    // stage W packed tf32 tiles (2048 uint4, 16 per thread)
#pragma unroll
    for (int i = 0; i < 16; i++) {
        const int e = t + 128 * i;
        const int kq = e >> 6;
        const int n = e & 63;
        const int k = (kq >> 2) * 8 + (kq & 3);
        const float w0 = __ldg(W + k * 64 + n);
        const float w1 = __ldg(W + (k + 4) * 64 + n);
        const float h0 = trunc16(w0), h1 = trunc16(w1);
        wpk[kq * WSTR + n] = make_uint4(__float_as_uint(h0), __float_as_uint(w0 - h0),
                                        __float_as_uint(h1), __float_as_uint(w1 - h1));
    }
    avs[t] = __ldg(av + t);
    __syncthreads();

    // ballots -> mask words
#pragma unroll
    for (int j = 0; j < 16; j++) {
        const uint32_t m = __ballot_sync(0xffffffffu, mv[j] > 0.5f);
        if (lane == 0) g_mask[gw4 * 16 + j] = m;
    }

    // 3xTF32 MMA k-loop: warp owns rows row0 + wid*16 .. +15
    float D[8][4];
#pragma unroll
    for (int nb = 0; nb < 8; nb++)
#pragma unroll
        for (int q = 0; q < 4; q++) D[nb][q] = 0.f;

    const float* arow = tin + (wid * 16 + r0) * ISTR;
#pragma unroll
    for (int kk = 0; kk < 8; kk++) {
        const int kb = kk * 8 + c0;
        const float i0 = arow[kb];
        const float i1 = arow[8 * ISTR + kb];
        const float i2 = arow[kb + 4];
        const float i3 = arow[8 * ISTR + kb + 4];
        const float h0 = trunc16(i0), h1 = trunc16(i1), h2 = trunc16(i2), h3 = trunc16(i3);
        const uint32_t ah0 = __float_as_uint(h0), ah1 = __float_as_uint(h1);
        const uint32_t ah2 = __float_as_uint(h2), ah3 = __float_as_uint(h3);
        const uint32_t al0 = __float_as_uint(i0 - h0), al1 = __float_as_uint(i1 - h1);
        const uint32_t al2 = __float_as_uint(i2 - h2), al3 = __float_as_uint(i3 - h3);

        const uint4* wrow = wpk + (kk * 4 + c0) * WSTR + r0;
#pragma unroll
        for (int nb = 0; nb < 8; nb++) {
            const uint4 bv = wrow[nb * 8];
            mma_tf32(D[nb], ah0, ah1, ah2, ah3, bv.x, bv.z);  // ah * wh
            mma_tf32(D[nb], ah0, ah1, ah2, ah3, bv.y, bv.w);  // ah * wl
            mma_tf32(D[nb], al0, al1, al2, al3, bv.x, bv.z);  // al * wh
        }
    }

    // dots from D fragments
    float ssA = 0.f, ssB = 0.f, sdA = 0.f, sdB = 0.f;
#pragma unroll
    for (int nb = 0; nb < 8; nb++) {
        const int c = nb * 8 + 2 * c0;
        ssA += D[nb][0] * avs[c] + D[nb][1] * avs[c + 1];
        ssB += D[nb][2] * avs[c] + D[nb][3] * avs[c + 1];
        sdA += D[nb][0] * avs[64 + c] + D[nb][1] * avs[64 + c + 1];
        sdB += D[nb][2] * avs[64 + c] + D[nb][3] * avs[64 + c + 1];
    }
#pragma unroll
    for (int o = 1; o <= 2; o <<= 1) {
        ssA += __shfl_xor_sync(0xffffffffu, ssA, o);
        ssB += __shfl_xor_sync(0xffffffffu, ssB, o);
        sdA += __shfl_xor_sync(0xffffffffu, sdA, o);
        sdB += __shfl_xor_sync(0xffffffffu, sdB, o);
    }
    if (c0 == 0) {
        const int rw = row0 + wid * 16 + r0;
        g_ssrc[rw] = ssA;
        g_ssrc[rw + 8] = ssB;
        g_sdst[rw] = sdA;
        g_sdst[rw + 8] = sdB;
    }
    float sdm = fmaxf(sdA, sdB);
#pragma unroll
    for (int o = 4; o <= 16; o <<= 1) sdm = fmaxf(sdm, __shfl_xor_sync(0xffffffffu, sdm, o));
    if (lane == 0) red[wid] = sdm;

    __syncthreads();   // k-loop wpk/tin reads done; safe to overwrite with ptile
    if (t == 0)
        atomicMax(&g_smaxu[b], enc_f(fmaxf(fmaxf(red[0], red[1]), fmaxf(red[2], red[3]))));

    // pair-build straight from D-fragments (validated in R15):
    // even-r0 lanes pair with lane^4 (rows +1).
    {
        const int qa = wid * 8 + (r0 >> 1);       // pair of rows base+r0, +1
        const int qb = qa + 4;                    // pair of rows base+8+r0, +1
        const int pra = ((qa >> 3) * 4 + (qa & 3)) * 2 + ((qa >> 2) & 1);
        const int prb = ((qb >> 3) * 4 + (qb & 3)) * 2 + ((qb >> 2) & 1);
        const bool even = (r0 & 1) == 0;
#pragma unroll
        for (int nb = 0; nb < 8; nb++) {
            const float p0 = __shfl_xor_sync(0xffffffffu, D[nb][0], 4);
            const float p1 = __shfl_xor_sync(0xffffffffu, D[nb][1], 4);
            const float p2 = __shfl_xor_sync(0xffffffffu, D[nb][2], 4);
            const float p3 = __shfl_xor_sync(0xffffffffu, D[nb][3], 4);
            if (even) {
                const int col = nb * 8 + 2 * c0;
                const float vals[4][2] = {{D[nb][0], p0}, {D[nb][1], p1},
                                          {D[nb][2], p2}, {D[nb][3], p3}};
                const int cols[4] = {col, col + 1, col, col + 1};
                const int prs[4] = {pra, pra, prb, prb};
#pragma unroll
                for (int u = 0; u < 4; u++) {
                    const float va = vals[u][0], vb = vals[u][1];
                    const __half ha = __float2half_rn(va);
                    const __half hb = __float2half_rn(vb);
                    uint2 pk;
                    pk.x = h2u(__halves2half2(ha, hb));
                    pk.y = h2u(__floats2half2_rn(va - __half2float(ha),
                                                 vb - __half2float(hb)));
                    ptile[cols[u] * PSTR2 + prs[u]] = pk;
                }
            }
        }
    }
    __syncthreads();

    // coalesced copy out (1024 uint4, 8 per thread)
    const uint4* pt4 = (const uint4*)ptile;
#pragma unroll
    for (int i = 0; i < 8; i++) {
        const int e = t + 128 * i;       // 0..1023
        const int c = e >> 4;
        const int m = e & 15;
        g_hpk4[((size_t)b * 64 + c) * 256 + n0 / 4 + m] = pt4[c * (PSTR2 / 2) + m];
    }
}

// ---------------------------------------------------------------------------
// Kernel C: factored-softmax coefficients (elementwise)
// ---------------------------------------------------------------------------
__global__ void __launch_bounds__(256) prep_kernel() {
    const int idx = blockIdx.x * 256 + threadIdx.x;
    const int b = idx >> 10;
    const float S = dec_f(g_smaxu[b]);
    const float ss = g_ssrc[idx];
    const float sd = g_sdst[idx];
    float mm = ss + S; mm = mm >= 0.f ? mm : 0.2f * mm;
    g_AB[idx] = make_float2(__expf(ss - mm), __expf(0.2f * ss - mm));
    g_EF[idx] = make_float2(__expf(sd), __expf(0.2f * sd));
}

// ---------------------------------------------------------------------------
// Kernel D: fused attention (R14-identical — its best measured config).
// ---------------------------------------------------------------------------
#define PKS4 20                              // uint4 stride per c-row
#define PKBUF4 (64 * PKS4)                   // uint4 per buffer (1280)
#define SMEM_DYN (4 * PKBUF4 * 16 + 4 * 64 * 8)
#define ONES2 0x3C003C00u

__global__ void __launch_bounds__(256, 2) attn_kernel(float* __restrict__ out) {
    extern __shared__ char sm[];
    uint4* pkbase = (uint4*)sm;
    float2* efbase = (float2*)(sm + 4 * PKBUF4 * 16);
    const uint32_t ef_addr0 = smem_u32(efbase);

    const int b = blockIdx.y;
    const int i0 = blockIdx.x * 128;
    const int t = threadIdx.x;
    const int w = t >> 5;
    const int lane = t & 31;
    const int r0 = lane >> 2;
    const int c0 = lane & 3;

    const int irow0 = i0 + w * 16 + r0;
    const int irow1 = irow0 + 8;

    const float2 ab0 = g_AB[b * N_ + irow0];
    const float2 ab1 = g_AB[b * N_ + irow1];
    const ULL AB0 = pack2f(ab0.x, ab0.y);
    const ULL AB1 = pack2f(ab1.x, ab1.y);

    float D[8][4];
#pragma unroll
    for (int nb = 0; nb < 8; nb++)
#pragma unroll
        for (int q = 0; q < 4; q++) D[nb][q] = 0.f;
    float Dl[4] = {0.f, 0.f, 0.f, 0.f};

    const uint32_t* mk0 = g_mask + (size_t)irow0 * 32;
    const uint32_t* mk1 = g_mask + (size_t)irow1 * 32;

    auto stage = [&](int jt) {
        const int buf = jt & 3;
        uint4* pkd = pkbase + buf * PKBUF4;
#pragma unroll
        for (int q = 0; q < 4; q++) {
            const int cid = q * 256 + t;
            const int c = cid >> 4;
            const int part = cid & 15;
            cp_async16(smem_u32(&pkd[c * PKS4 + part]),
                       &g_hpk4[((size_t)b * 64 + c) * 256 + jt * 16 + part]);
        }
        if (t < 32)
            cp_async16(smem_u32(&efbase[buf * 64 + t * 2]), &g_EF[b * N_ + jt * 64 + t * 2]);
    };

    stage(0); CP_COMMIT();
    stage(1); CP_COMMIT();
    stage(2); CP_COMMIT();

    uint32_t mw00 = __ldg(mk0 + 0), mw01 = __ldg(mk0 + 1);
    uint32_t mw10 = __ldg(mk1 + 0), mw11 = __ldg(mk1 + 1);

    for (int jt = 0; jt < 16; jt++) {
        CP_WAIT2();
        __syncthreads();

        if (jt + 3 < 16) stage(jt + 3);
        CP_COMMIT();

        const int jw = (jt < 15) ? (jt + 1) * 2 : 0;
        const uint32_t nw00 = __ldg(mk0 + jw), nw01 = __ldg(mk0 + jw + 1);
        const uint32_t nw10 = __ldg(mk1 + jw), nw11 = __ldg(mk1 + jw + 1);

        const int buf = jt & 3;
        const uint4* pkp = pkbase + buf * PKBUF4;
        const uint32_t efs = ef_addr0 + buf * 512 + 2 * c0 * 8;

        const uint32_t wsh00 = mw00 >> (2 * c0), wsh01 = mw01 >> (2 * c0);
        const uint32_t wsh10 = mw10 >> (2 * c0), wsh11 = mw11 >> (2 * c0);

#pragma unroll
        for (int ks = 0; ks < 4; ks++) {
            const uint32_t ea_addr = efs + ks * 16 * 8;
            const ULL ea = ld_s64(ea_addr);
            const ULL eb = ld_s64(ea_addr + 8);
            const ULL ec = ld_s64(ea_addr + 64);
            const ULL ed = ld_s64(ea_addr + 72);
            const uint32_t ws0 = (ks < 2) ? wsh00 : wsh01;
            const uint32_t ws1 = (ks < 2) ? wsh10 : wsh11;
            const int bo = (ks & 1) << 4;

            float2 q;
            q = mul2f(AB0, ea); float p00 = fmaxf(q.x, q.y);
            q = mul2f(AB0, eb); float p01 = fmaxf(q.x, q.y);
            q = mul2f(AB0, ec); float p02 = fmaxf(q.x, q.y);
            q = mul2f(AB0, ed); float p03 = fmaxf(q.x, q.y);
            q = mul2f(AB1, ea); float p10 = fmaxf(q.x, q.y);
            q = mul2f(AB1, eb); float p11 = fmaxf(q.x, q.y);
            q = mul2f(AB1, ec); float p12 = fmaxf(q.x, q.y);
            q = mul2f(AB1, ed); float p13 = fmaxf(q.x, q.y);

            p00 = ((ws0 >> (bo + 0)) & 1u) ? p00 : 0.f;
            p01 = ((ws0 >> (bo + 1)) & 1u) ? p01 : 0.f;
            p02 = ((ws0 >> (bo + 8)) & 1u) ? p02 : 0.f;
            p03 = ((ws0 >> (bo + 9)) & 1u) ? p03 : 0.f;
            p10 = ((ws1 >> (bo + 0)) & 1u) ? p10 : 0.f;
            p11 = ((ws1 >> (bo + 1)) & 1u) ? p11 : 0.f;
            p12 = ((ws1 >> (bo + 8)) & 1u) ? p12 : 0.f;
            p13 = ((ws1 >> (bo + 9)) & 1u) ? p13 : 0.f;

            const float t00 = trunc16(p00), t01 = trunc16(p01);
            const float t02 = trunc16(p02), t03 = trunc16(p03);
            const float t10 = trunc16(p10), t11 = trunc16(p11);
            const float t12 = trunc16(p12), t13 = trunc16(p13);

            const uint32_t uh0 = h2u(__floats2half2_rn(t00, t01));
            const uint32_t uh1 = h2u(__floats2half2_rn(t10, t11));
            const uint32_t uh2 = h2u(__floats2half2_rn(t02, t03));
            const uint32_t uh3 = h2u(__floats2half2_rn(t12, t13));
            const uint32_t ul0 = h2u(__floats2half2_rn(p00 - t00, p01 - t01));
            const uint32_t ul1 = h2u(__floats2half2_rn(p10 - t10, p11 - t11));
            const uint32_t ul2 = h2u(__floats2half2_rn(p02 - t02, p03 - t03));
            const uint32_t ul3 = h2u(__floats2half2_rn(p12 - t12, p13 - t13));

            // l = Σ(ph + pl) — both terms (ph-only measured too lossy in R12)
            mma_f16(Dl, uh0, uh1, uh2, uh3, ONES2, ONES2);
            mma_f16(Dl, ul0, ul1, ul2, ul3, ONES2, ONES2);

#pragma unroll
            for (int nb = 0; nb < 8; nb++) {
                const uint4 bv = pkp[(nb * 8 + r0) * PKS4 + ks * 4 + c0];
                mma_f16(D[nb], uh0, uh1, uh2, uh3, bv.x, bv.z);  // ph * hh
                mma_f16(D[nb], uh0, uh1, uh2, uh3, bv.y, bv.w);  // ph * hl
                mma_f16(D[nb], ul0, ul1, ul2, ul3, bv.x, bv.z);  // pl * hh
            }
        }

        mw00 = nw00; mw01 = nw01; mw10 = nw10; mw11 = nw11;
    }

    const float inv0 = 1.0f / Dl[0];
    const float inv1 = 1.0f / Dl[2];

    float2* o0 = (float2*)(out + ((size_t)b * N_ + irow0) * C_ + 2 * c0);
    float2* o1 = (float2*)(out + ((size_t)b * N_ + irow1) * C_ + 2 * c0);
#pragma unroll
    for (int nb = 0; nb < 8; nb++) {
        float v0 = D[nb][0] * inv0;
        float v1 = D[nb][1] * inv0;
        float v2 = D[nb][2] * inv1;
        float v3 = D[nb][3] * inv1;
        v0 = v0 > 0.f ? v0 : (__expf(v0) - 1.0f);
        v1 = v1 > 0.f ? v1 : (__expf(v1) - 1.0f);
        v2 = v2 > 0.f ? v2 : (__expf(v2) - 1.0f);
        v3 = v3 > 0.f ? v3 : (__expf(v3) - 1.0f);
        o0[nb * 4] = make_float2(v0, v1);
        o1[nb * 4] = make_float2(v2, v3);
    }
}

// ---------------------------------------------------------------------------
extern "C" void kernel_launch(void* const* d_in, const int* in_sizes, int n_in,
                              void* d_out, int out_size) {
    const float* input = (const float*)d_in[0];  // (32,1024,64)
    const float* adj   = (const float*)d_in[1];  // (1024,1024)
    const float* W     = (const float*)d_in[2];  // (64,64)
    const float* a     = (const float*)d_in[3];  // (128,1)
    float* out = (float*)d_out;

    cudaFuncSetAttribute(gemm_h_kernel, cudaFuncAttributeMaxDynamicSharedMemorySize, GS_TOTAL);
    cudaFuncSetAttribute(attn_kernel, cudaFuncAttributeMaxDynamicSharedMemorySize, SMEM_DYN);

    gemm_h_kernel<<<BN / 64, 128, GS_TOTAL>>>(input, W, a, adj);
    prep_kernel<<<BN / 256, 256>>>();
    attn_kernel<<<dim3(N_ / 128, B_), 256, SMEM_DYN>>>(out);
}